// round 17
// baseline (speedup 1.0000x reference)
#include <cuda_runtime.h>
#include <cuda_fp16.h>
#include <cstdint>

#define NROWS   131072
#define HD      128
#define NSTEPS  12
#define MROWS   64
#define NBLK    (NROWS / MROWS)
#define NTHREADS 256
#define HS_STRIDE ((size_t)NROWS * HD)
#define LO_SCALE   1024.0f
#define LO_INV     (1.0f / 1024.0f)

// ---------------- SMEM layout (byte offsets) -------------------------------
// fp16 tiles: rows x 512B (256 fp16); fp8 tiles: rows x 256B. 16B-chunk
// swizzle: chunk ^= (row&7).  K INTERLEAVED: k' = 2h -> cos/W_cos col h,
// k' = 2h+1 -> sin/W_sin col h.
#define OFF_WH   0        // W hi fp16: 128 x 512B                  64 KB
#define OFF_W8H  65536    // W fp8 (e4m3 of full W): 128 x 256B     32 KB
#define OFF_W8L  98304    // W lo*1024 fp8: 128 x 256B              32 KB
#define OFF_FH   131072   // feats hi fp16: 64 x 512B               32 KB
#define OFF_F8H  163840   // feats fp8: 64 x 256B                   16 KB
#define OFF_F8L  180224   // feats lo*1024 fp8: 64 x 256B           16 KB
#define OFF_XDB  196608   // xdb: [16 float2-pairs][256 thr]        32 KB
#define OFF_EW   196608   // e_w (prologue only; overlays XDB)
#define OFF_EB   197120   // e_b (prologue only; overlays XDB)
#define OFF_DB   229376
#define OFF_K1   229888
#define OFF_RW   230400   // 3*128 floats
#define OFF_OUT  231936
#define OFF_RB   232192
#define SMEM_TOTAL 232208

// ======================= low-level helpers =================================
static __device__ __forceinline__ uint32_t smem_u32(const void* p) {
    uint32_t a;
    asm("{ .reg .u64 t; cvta.to.shared.u64 t, %1; cvt.u32.u64 %0, t; }" : "=r"(a) : "l"(p));
    return a;
}
static __device__ __forceinline__ void ldmx4(uint32_t* a, uint32_t addr) {
    asm volatile("ldmatrix.sync.aligned.m8n8.x4.shared.b16 {%0,%1,%2,%3}, [%4];"
                 : "=r"(a[0]), "=r"(a[1]), "=r"(a[2]), "=r"(a[3]) : "r"(addr));
}
// fp16 main-pass mma, fp32 accum
static __device__ __forceinline__ void mma16816(float* c, const uint32_t* a, const uint32_t* b) {
    asm volatile("mma.sync.aligned.m16n8k16.row.col.f32.f16.f16.f32 "
                 "{%0,%1,%2,%3}, {%4,%5,%6,%7}, {%8,%9}, {%0,%1,%2,%3};"
                 : "+f"(c[0]), "+f"(c[1]), "+f"(c[2]), "+f"(c[3])
                 : "r"(a[0]), "r"(a[1]), "r"(a[2]), "r"(a[3]), "r"(b[0]), "r"(b[1]));
}
// fp8 e4m3 correction mma, k32, fp32 accum
static __device__ __forceinline__ void mma8(float* c, const uint32_t* a, const uint32_t* b) {
    asm volatile("mma.sync.aligned.m16n8k32.row.col.f32.e4m3.e4m3.f32 "
                 "{%0,%1,%2,%3}, {%4,%5,%6,%7}, {%8,%9}, {%0,%1,%2,%3};"
                 : "+f"(c[0]), "+f"(c[1]), "+f"(c[2]), "+f"(c[3])
                 : "r"(a[0]), "r"(a[1]), "r"(a[2]), "r"(a[3]), "r"(b[0]), "r"(b[1]));
}

// mt-group barrier: the 128 threads (4 warps) of m-tile group mt
#define GROUP_BAR(id) asm volatile("bar.sync %0, 128;" :: "r"(id) : "memory")

// fp16 hi of pair (a->lo, b->hi) + f32 residuals * LO_SCALE
static __device__ __forceinline__ uint32_t hi_and_res(float a, float b, float2& res) {
    __half2 h2 = __floats2half2_rn(a, b);
    float2 f2 = __half22float2(h2);
    res.x = (a - f2.x) * LO_SCALE;
    res.y = (b - f2.y) * LO_SCALE;
    return *reinterpret_cast<uint32_t*>(&h2);
}
// pack 4 floats -> 4 e4m3 bytes {c0, s0, c1, s1}
static __device__ __forceinline__ uint32_t pack_e4m3x4(float c0, float s0, float c1, float s1) {
    unsigned short p0, p1;
    asm("cvt.rn.satfinite.e4m3x2.f32 %0, %1, %2;" : "=h"(p0) : "f"(s0), "f"(c0));
    asm("cvt.rn.satfinite.e4m3x2.f32 %0, %1, %2;" : "=h"(p1) : "f"(s1), "f"(c1));
    return (uint32_t)p0 | ((uint32_t)p1 << 16);
}

// 8B store into a swizzled 512B-row fp16 tile
static __device__ __forceinline__ void st8sw(char* sm, int off, int r, int cbyte, uint2 v) {
    uint32_t chunk = ((uint32_t)(cbyte >> 4)) ^ (uint32_t)(r & 7);
    *(uint2*)(sm + off + r * 512 + (chunk << 4) + (cbyte & 15)) = v;
}
// 4B store into a swizzled 256B-row fp8 tile
static __device__ __forceinline__ void st4f8(char* sm, int off, int r, int cbyte, uint32_t v) {
    uint32_t chunk = ((uint32_t)(cbyte >> 4)) ^ (uint32_t)(r & 7);
    *(uint32_t*)(sm + off + r * 256 + (chunk << 4) + (cbyte & 15)) = v;
}

// Emit (cos,sin) for row r, cols cj, cj+1: fp16 hi (8B) + fp8 full (4B) + fp8 lo (4B)
static __device__ __forceinline__ void emit_feats(char* sm, int r, int cj,
                                                  float c0, float c1, float s0, float s1) {
    float2 r0v, r1v;
    uint32_t h0 = hi_and_res(c0, s0, r0v);
    uint32_t h1 = hi_and_res(c1, s1, r1v);
    st8sw(sm, OFF_FH, r, 4 * cj, make_uint2(h0, h1));
    st4f8(sm, OFF_F8H, r, 2 * cj, pack_e4m3x4(c0, s0, c1, s1));
    st4f8(sm, OFF_F8L, r, 2 * cj, pack_e4m3x4(r0v.x, r0v.y, r1v.x, r1v.y));
}

// Stage 128x256 fp32 weight block (d_w cols [colbase, colbase+256)) -> WH fp16,
// W8H fp8(W), W8L fp8(Wl*1024).  256 threads: (row = tid>>1, half = tid&1).
static __device__ __forceinline__ void stage_w(char* sm, const float* __restrict__ dw,
                                               int colbase, int tid) {
    int r = tid >> 1, half = tid & 1;
    const float* base = dw + (size_t)r * 512 + colbase;
    int rx = r & 7;
    char* dh = sm + OFF_WH + r * 512;
    char* d8h = sm + OFF_W8H + r * 256;
    char* d8l = sm + OFF_W8L + r * 256;
#pragma unroll
    for (int i = 0; i < 16; i++) {
        int ii = half * 16 + i;                       // fp16 16B-chunk index (covers 4 h-cols)
        float4 c = *(const float4*)(base + 4 * ii);
        float4 s = *(const float4*)(base + 128 + 4 * ii);
        float2 e0, e1, e2, e3;
        uint4 h;
        h.x = hi_and_res(c.x, s.x, e0);
        h.y = hi_and_res(c.y, s.y, e1);
        h.z = hi_and_res(c.z, s.z, e2);
        h.w = hi_and_res(c.w, s.w, e3);
        *(uint4*)(dh + ((uint32_t)(ii ^ rx) << 4)) = h;
        uint2 v8h = make_uint2(pack_e4m3x4(c.x, s.x, c.y, s.y),
                               pack_e4m3x4(c.z, s.z, c.w, s.w));
        uint2 v8l = make_uint2(pack_e4m3x4(e0.x, e0.y, e1.x, e1.y),
                               pack_e4m3x4(e2.x, e2.y, e3.x, e3.y));
        uint32_t ch8 = (((uint32_t)(ii >> 1)) ^ (uint32_t)rx) << 4;
        uint32_t sub = (uint32_t)(ii & 1) * 8;
        *(uint2*)(d8h + ch8 + sub) = v8h;
        *(uint2*)(d8l + ch8 + sub) = v8l;
    }
}

// Main pass: C(f32) += Ah(fp16) @ Wh(fp16)^T, K=256, warp tile 32x32.
static __device__ __forceinline__ void gemm_main(uint32_t sb, int lane, float* C,
                                                 int Rbase, int n0) {
    const int rx  = lane & 7;
    const int r   = Rbase + rx + ((lane >> 3) & 1) * 8;
    const int kpa = lane >> 4;
    const int kpb = (lane >> 3) & 1;
    const int jb  = (lane >> 4) & 1;
    const uint32_t aH = sb + OFF_FH + r * 512;
    const uint32_t bH = sb + OFF_WH + (uint32_t)((n0 + rx) * 512 + jb * 4096);
#pragma unroll 4
    for (int kt = 0; kt < 16; kt++) {
        uint32_t aoff = (uint32_t)(((2 * kt + kpa) ^ rx) << 4);
        uint32_t boff = (uint32_t)(((2 * kt + kpb) ^ rx) << 4);
        uint32_t ah0[4], ah1[4];
        ldmx4(ah0, aH + aoff);
        ldmx4(ah1, aH + 8192 + aoff);                 // rows +16
#pragma unroll
        for (int jp = 0; jp < 2; jp++) {
            uint32_t bh[4];
            ldmx4(bh, bH + jp * 8192 + boff);
            mma16816(C + jp * 8,          ah0, bh);
            mma16816(C + jp * 8 + 4,      ah0, bh + 2);
            mma16816(C + 16 + jp * 8,     ah1, bh);
            mma16816(C + 16 + jp * 8 + 4, ah1, bh + 2);
        }
    }
}

// Correction pass (fp8): Cw += Al8@W8 + A8@Wl8;  C += Cw/1024.  k32 units.
static __device__ __forceinline__ void gemm_corr(uint32_t sb, int lane, float* C,
                                                 int Rbase, int n0) {
    float Cw[32];
#pragma unroll
    for (int i = 0; i < 32; i++) Cw[i] = 0.f;
    const int rx  = lane & 7;
    const int r   = Rbase + rx + ((lane >> 3) & 1) * 8;
    const int kpa = lane >> 4;
    const int kpb = (lane >> 3) & 1;
    const int jb  = (lane >> 4) & 1;
    const uint32_t aH8 = sb + OFF_F8H + r * 256;
    const uint32_t aL8 = sb + OFF_F8L + r * 256;
    const uint32_t b8row = (uint32_t)((n0 + rx) * 256 + jb * 2048);
    const uint32_t bH8 = sb + OFF_W8H + b8row;
    const uint32_t bL8 = sb + OFF_W8L + b8row;
#pragma unroll 2
    for (int ku = 0; ku < 8; ku++) {
        uint32_t aoff = (uint32_t)(((2 * ku + kpa) ^ rx) << 4);
        uint32_t boff = (uint32_t)(((2 * ku + kpb) ^ rx) << 4);
        uint32_t ah0[4], ah1[4], al0[4], al1[4];
        ldmx4(ah0, aH8 + aoff);
        ldmx4(ah1, aH8 + 4096 + aoff);                // rows +16 (16*256B)
        ldmx4(al0, aL8 + aoff);
        ldmx4(al1, aL8 + 4096 + aoff);
#pragma unroll
        for (int jp = 0; jp < 2; jp++) {
            uint32_t bh[4], bl[4];
            ldmx4(bh, bH8 + jp * 4096 + boff);        // n8 pair (16 rows * 256B)
            ldmx4(bl, bL8 + jp * 4096 + boff);
            float* w0 = Cw + jp * 8;
            float* w1 = Cw + 16 + jp * 8;
            mma8(w0,     al0, bh);      mma8(w0 + 4, al0, bh + 2);
            mma8(w1,     al1, bh);      mma8(w1 + 4, al1, bh + 2);
            mma8(w0,     ah0, bl);      mma8(w0 + 4, ah0, bl + 2);
            mma8(w1,     ah1, bl);      mma8(w1 + 4, ah1, bl + 2);
        }
    }
#pragma unroll
    for (int i = 0; i < 32; i++) C[i] = fmaf(Cw[i], LO_INV, C[i]);
}

// ======================= kernel ============================================
__global__ void __launch_bounds__(NTHREADS, 1)
phase_kernel(const float* __restrict__ x, const float* __restrict__ e_w,
             const float* __restrict__ e_b, const float* __restrict__ d_w,
             const float* __restrict__ d_b, const float* __restrict__ r_w,
             const float* __restrict__ r_b, float* __restrict__ outbuf) {
    extern __shared__ char sm[];
    float* smf = (float*)sm;
    float2* xdb2 = (float2*)(sm + OFF_XDB);      // [16 pairs][256 threads]
    const int tid  = threadIdx.x;
    const int lane = tid & 31;
    const int warp = tid >> 5;
    const int mt = warp >> 2, nq = warp & 3;     // m-group (0..1), n-quarter (0..3)
    const int Rbase = mt * 32, n0 = nq * 32;
    const int gbar = 1 + mt;
    const int g  = lane >> 2;
    const int c2 = (lane & 3) * 2;
    const int r0 = Rbase + g;                    // rows r0, r0+8, r0+16, r0+24
    const int grow0 = blockIdx.x * MROWS + r0;
    const uint32_t sb = smem_u32(sm);

    // ---- stage small arrays; exact K1 = rowsum(Wcs cos-half) ----
    if (tid < 128) {
        smf[OFF_EW / 4 + tid] = e_w[tid];
        smf[OFF_EB / 4 + tid] = e_b[tid];
        smf[OFF_DB / 4 + tid] = d_b[tid];
        smf[OFF_RW / 4 + tid]       = r_w[tid];
        smf[OFF_RW / 4 + 128 + tid] = r_w[128 + tid];
        smf[OFF_RW / 4 + 256 + tid] = r_w[256 + tid];
        const float4* wr = (const float4*)(d_w + (size_t)tid * 512);
        float s = 0.f;
#pragma unroll 8
        for (int i = 0; i < 32; i++) {
            float4 v = wr[i];
            s += v.x + v.y + v.z + v.w;
        }
        smf[OFF_K1 / 4 + tid] = s;
    }
    if (tid < MROWS) smf[OFF_OUT / 4 + tid] = 0.f;
    if (tid == 0) smf[OFF_RB / 4] = r_b[0];

    stage_w(sm, d_w, 256, tid);                  // Wx = d_w[:, 256:512]
    __syncthreads();

    float xv[4];
#pragma unroll
    for (int q = 0; q < 4; q++) xv[q] = x[grow0 + 8 * q];

    // ---- xp feats: cos/sin(x*e_w + e_b), 4 rows x 8 cols per thread ----
#pragma unroll
    for (int j = 0; j < 4; j++) {
        int cj = n0 + 8 * j + c2;
        float w0 = smf[OFF_EW / 4 + cj], w1 = smf[OFF_EW / 4 + cj + 1];
        float b0 = smf[OFF_EB / 4 + cj], b1 = smf[OFF_EB / 4 + cj + 1];
#pragma unroll
        for (int q = 0; q < 4; q++) {
            float p0 = fmaf(xv[q], w0, b0), p1 = fmaf(xv[q], w1, b1);
            float s0, c0, s1, c1;
            __sincosf(p0, &s0, &c0); __sincosf(p1, &s1, &c1);
            emit_feats(sm, r0 + 8 * q, cj, c0, c1, s0, s1);
        }
    }
    __syncthreads();

    float C[32];
#pragma unroll
    for (int i = 0; i < 32; i++) C[i] = 0.f;

    gemm_main(sb, lane, C, Rbase, n0);           // C  = Ah@Wx_h
    gemm_corr(sb, lane, C, Rbase, n0);           // C += fp8 corrections -> X0
    __syncthreads();                             // all reads of Wx/feats done

    // xdb = X0 + d_b -> smem; C <- X0 + K1 + d_b = ph(1)  (d_b pre-folded)
#pragma unroll
    for (int i = 0; i < 16; i++) {
        int ci = 2 * i;
        int cj = n0 + 8 * ((ci & 15) >> 2) + c2;
        float d0 = smf[OFF_DB / 4 + cj], d1 = smf[OFF_DB / 4 + cj + 1];
        float k0 = smf[OFF_K1 / 4 + cj], k1v = smf[OFF_K1 / 4 + cj + 1];
        xdb2[i * 256 + tid] = make_float2(C[ci] + d0, C[ci + 1] + d1);
        C[ci]     += k0 + d0;
        C[ci + 1] += k1v + d1;
    }

    stage_w(sm, d_w, 0, tid);                    // Wcs = d_w[:, 0:256]
    __syncthreads();                             // Wcs visible; feats tile free

    float* hst = outbuf + NROWS;                 // Hstack [12, B, 128]
    float racc[4] = {0.f, 0.f, 0.f, 0.f};

    // ---- recurrence.  At loop top: ph_t = C + (t-1)*xdb (d_b pre-folded). ----
#pragma unroll 1
    for (int t = 1; t <= NSTEPS; t++) {
        const float tm1 = (float)(t - 1);
        float* hb = hst + (size_t)(t - 1) * HS_STRIDE + (size_t)grow0 * HD;
#pragma unroll
        for (int mi = 0; mi < 2; mi++)
#pragma unroll
            for (int j = 0; j < 4; j++) {
                int cj = n0 + 8 * j + c2;
                int ci = mi * 16 + j * 4;
                float2 xd0 = xdb2[(ci >> 1) * 256 + tid];
                float2 xd1 = xdb2[(ci >> 1) * 256 + 256 + tid];
                float p0 = fmaf(tm1, xd0.x, C[ci + 0]);
                float p1 = fmaf(tm1, xd0.y, C[ci + 1]);
                float p2 = fmaf(tm1, xd1.x, C[ci + 2]);
                float p3 = fmaf(tm1, xd1.y, C[ci + 3]);
                __stcs((float2*)(hb + (16 * mi) * HD + cj),     make_float2(p0, p1));
                __stcs((float2*)(hb + (16 * mi + 8) * HD + cj), make_float2(p2, p3));
                float s0, cv0, s1, cv1, s2, cv2, s3, cv3;
                __sincosf(p0, &s0, &cv0); __sincosf(p1, &s1, &cv1);
                __sincosf(p2, &s2, &cv2); __sincosf(p3, &s3, &cv3);
                if (t < NSTEPS) {
                    emit_feats(sm, r0 + 16 * mi,     cj, cv0, cv1, s0, s1);
                    emit_feats(sm, r0 + 16 * mi + 8, cj, cv2, cv3, s2, s3);
                } else {
                    float w0 = smf[OFF_RW / 4 + cj],       w1 = smf[OFF_RW / 4 + cj + 1];
                    float v0 = smf[OFF_RW / 4 + 128 + cj], v1 = smf[OFF_RW / 4 + 128 + cj + 1];
                    float u0 = smf[OFF_RW / 4 + 256 + cj], u1 = smf[OFF_RW / 4 + 256 + cj + 1];
                    float a0 = racc[2 * mi], a1 = racc[2 * mi + 1];
                    a0 = fmaf(cv0, w0, a0); a0 = fmaf(s0, v0, a0); a0 = fmaf(p0, u0, a0);
                    a0 = fmaf(cv1, w1, a0); a0 = fmaf(s1, v1, a0); a0 = fmaf(p1, u1, a0);
                    a1 = fmaf(cv2, w0, a1); a1 = fmaf(s2, v0, a1); a1 = fmaf(p2, u0, a1);
                    a1 = fmaf(cv3, w1, a1); a1 = fmaf(s3, v1, a1); a1 = fmaf(p3, u1, a1);
                    racc[2 * mi] = a0; racc[2 * mi + 1] = a1;
                }
            }
        if (t < NSTEPS) {
            GROUP_BAR(gbar);                     // group's feats(ph_t) written
            gemm_main(sb, lane, C, Rbase, n0);
            gemm_corr(sb, lane, C, Rbase, n0);   // C += feats @ Wcs^T
            GROUP_BAR(gbar);                     // group done reading feats
        }
    }

    // ---- reduce readout across quad lanes, then across the 4 n-quarter warps ----
#pragma unroll
    for (int q = 0; q < 4; q++) {
        racc[q] += __shfl_xor_sync(0xffffffffu, racc[q], 1);
        racc[q] += __shfl_xor_sync(0xffffffffu, racc[q], 2);
    }
    if ((lane & 3) == 0) {
        atomicAdd(&smf[OFF_OUT / 4 + r0],      racc[0]);
        atomicAdd(&smf[OFF_OUT / 4 + r0 + 8],  racc[1]);
        atomicAdd(&smf[OFF_OUT / 4 + r0 + 16], racc[2]);
        atomicAdd(&smf[OFF_OUT / 4 + r0 + 24], racc[3]);
    }
    __syncthreads();
    if (tid < MROWS)
        outbuf[blockIdx.x * MROWS + tid] = smf[OFF_OUT / 4 + tid] + smf[OFF_RB / 4];
}

extern "C" void kernel_launch(void* const* d_in, const int* in_sizes, int n_in,
                              void* d_out, int out_size) {
    const float* x   = (const float*)d_in[0];
    const float* e_w = (const float*)d_in[1];
    const float* e_b = (const float*)d_in[2];
    const float* d_w = (const float*)d_in[3];
    const float* d_b = (const float*)d_in[4];
    const float* r_w = (const float*)d_in[5];
    const float* r_b = (const float*)d_in[6];
    float* out = (float*)d_out;

    cudaFuncSetAttribute(phase_kernel,
                         cudaFuncAttributeMaxDynamicSharedMemorySize, SMEM_TOTAL);
    phase_kernel<<<NBLK, NTHREADS, SMEM_TOTAL>>>(x, e_w, e_b, d_w, d_b, r_w, r_b, out);
}